// round 15
// baseline (speedup 1.0000x reference)
#include <cuda_runtime.h>
#include <cuda_fp16.h>
#include <stdint.h>

// Problem constants
#define B_ 1024
#define I_ 256
#define O_ 256
#define K_ 128

#define NSEG 8          // i-segments: grid = 32 b-tiles x 8 = 256 CTAs (0.86 wave at occ 2)
#define ISEG (I_ / NSEG)
#define BTILE 32        // batches per CTA
#define KSPLIT 4        // prepack k-parallelism / prep b-slice

// Per-(b,i) fp32 packed activation [i][b]: (silu, 1-frac, frac, bitcast(l*1024))
__device__ float4 g_pkf[I_ * B_];
// Packed spline pairs [i][k][o] = half2(c[o,i,k]*s, c[o,i,k+1]*s)  (33.5 MB, L2-resident)
__device__ unsigned int g_pre[(size_t)I_ * K_ * O_];
// Transposed base weights [i][o]
__device__ float g_bwT[I_ * O_];
// Exclusive partial sums per i-segment
__device__ float g_part[NSEG][B_][O_];
// Arrival counters per b-tile (reset by the reducing CTA)
__device__ int g_cnt[B_ / BTILE];

__device__ __forceinline__ unsigned int h2bits(__half2 h) {
    return *reinterpret_cast<unsigned int*>(&h);
}
__device__ __forceinline__ float2 bits2f2(unsigned int u) {
    return __half22float2(*reinterpret_cast<__half2*>(&u));
}

// Fused preprocessing: activation prep (one (i,b) per thread) + coefficient prepack
// (one (i, k-chunk, o) per thread) + bw transpose. Grid (I_, KSPLIT) x 256.
__global__ __launch_bounds__(256) void prepack_kernel(
    const float* __restrict__ x,      // [B, I]
    const float* __restrict__ coeff,  // [O, I, K]
    const float* __restrict__ scale,  // [O, I]
    const float* __restrict__ bw)     // [O, I]
{
    const int i = blockIdx.x;
    const int y = blockIdx.y;
    const int o = threadIdx.x;

    // ---- prep slice: b = y*256 + o ----
    {
        const int b = y * 256 + o;
        float xv = __ldg(&x[b * I_ + i]);
        float ax = fabsf(xv);
        float e  = __expf(-2.0f * ax);
        float r  = (1.0f - e) / (1.0f + e);
        float p  = copysignf(r, xv);              // tanh(x) in [-1,1] => clip identity
        float sg = 1.0f / (1.0f + __expf(-p));
        float act = p * sg;                        // silu(p)
        float scaled = fminf(fmaxf((p + 1.0f) * 63.5f, 0.0f), 127.0f);
        int   l    = (int)scaled;
        float frac = scaled - (float)l;
        g_pkf[i * B_ + b] = make_float4(act, 1.0f - frac, frac,
                                        __int_as_float(l * (O_ * 4)));
    }

    // ---- prepack slice: k-chunk [y*32, y*32+32) for output o ----
    const int kb = y * (K_ / KSPLIT);
    const float* src = coeff + ((size_t)o * I_ + i) * (size_t)K_;
    float s = __ldg(&scale[o * I_ + i]);
    unsigned int* dst = g_pre + (size_t)i * (K_ * O_) + (size_t)kb * O_ + o;

    float c[33];
    const float4* s4 = (const float4*)(src + kb);
#pragma unroll
    for (int j = 0; j < 8; j++) {
        float4 v = s4[j];
        c[4 * j] = v.x; c[4 * j + 1] = v.y; c[4 * j + 2] = v.z; c[4 * j + 3] = v.w;
    }
    // Right-tap of the chunk's last k: next element, or wrap (only read at l=127 where frac=0)
    c[32] = (kb + 32 < K_) ? __ldg(src + kb + 32) : __ldg(src);

#pragma unroll
    for (int k = 0; k < 32; k++)
        dst[(size_t)k * O_] = h2bits(__floats2half2_rn(c[k] * s, c[k + 1] * s));

    if (y == 0)
        g_bwT[i * O_ + o] = __ldg(&bw[o * I_ + i]);   // coalesced write
}

// Main: barrier-free hot loop; LDG.64 gathers serve 2 outputs per lane, 8 in flight per warp.
// 512 threads = 16 warps: warp = (o-group 0..3, 64 o's) x (b-quarter 0..3, 8 batches).
__global__ __launch_bounds__(512, 2) void kan_main(
    const float* __restrict__ bias, float* __restrict__ out)
{
    __shared__ __align__(16) float4 sPk[ISEG * BTILE];   // 16 KB
    __shared__ int sLast;

    const int tid  = threadIdx.x;
    const int lane = tid & 31;
    const int warp = tid >> 5;
    const int og   = warp & 3;        // o-group of 64 outputs
    const int bq   = warp >> 2;       // b-quarter (8 batches)
    const int o0   = og * 64;
    const int ol   = o0 + 2 * lane;   // this lane's output pair (ol, ol+1)
    const int b0   = blockIdx.x * BTILE;
    const int ibeg = blockIdx.y * ISEG;

    // Stage pk for the whole segment (coalesced LDG.128; only barrier before reduce)
    for (int t = tid; t < ISEG * BTILE; t += 512)
        sPk[t] = g_pkf[(ibeg + (t >> 5)) * B_ + b0 + (t & 31)];
    __syncthreads();

    float acc[8][2];
#pragma unroll
    for (int j = 0; j < 8; j++) { acc[j][0] = 0.0f; acc[j][1] = 0.0f; }

    for (int ii = 0; ii < ISEG; ii++) {
        const int i = ibeg + ii;
        const float2 wv = *(const float2*)(g_bwT + i * O_ + ol);   // coalesced LDG.64
        const char* gbase = (const char*)g_pre + ((size_t)i * (K_ * O_) + ol) * 4u;
        const float4* pkp = sPk + ii * BTILE + bq * 8;

        // Issue all 8 independent gathers first (MLP), then consume.
        float4 pk[8];
        uint2  ge[8];
#pragma unroll
        for (int bb = 0; bb < 8; bb++) {
            pk[bb] = pkp[bb];                                       // LDS.128 broadcast
            ge[bb] = *(const uint2*)(gbase + __float_as_int(pk[bb].w));  // 256B/warp
        }
#pragma unroll
        for (int bb = 0; bb < 8; bb++) {
            float2 c0 = bits2f2(ge[bb].x);                          // (c_l*s, c_r*s) for ol
            float2 c1 = bits2f2(ge[bb].y);                          // for ol+1
            acc[bb][0] = fmaf(pk[bb].y, c0.x, acc[bb][0]);
            acc[bb][0] = fmaf(pk[bb].z, c0.y, acc[bb][0]);
            acc[bb][0] = fmaf(pk[bb].x, wv.x, acc[bb][0]);
            acc[bb][1] = fmaf(pk[bb].y, c1.x, acc[bb][1]);
            acc[bb][1] = fmaf(pk[bb].z, c1.y, acc[bb][1]);
            acc[bb][1] = fmaf(pk[bb].x, wv.y, acc[bb][1]);
        }
    }

    // Exclusive partial slice (coalesced 256B rows via float2)
#pragma unroll
    for (int bb = 0; bb < 8; bb++)
        *(float2*)(&g_part[blockIdx.y][b0 + bq * 8 + bb][ol]) = make_float2(acc[bb][0], acc[bb][1]);

    // Last-arriving CTA of this b-tile reduces the NSEG partials (fixed order, deterministic)
    __threadfence();
    __syncthreads();
    if (tid == 0) {
        int old = atomicAdd(&g_cnt[blockIdx.x], 1);
        sLast = (old == NSEG - 1);
    }
    __syncthreads();
    if (sLast) {
#pragma unroll
        for (int j = 0; j < 4; j++) {
            int t  = tid + 512 * j;          // 2048 float4 = 32 b x 64 f4
            int bl = t >> 6;
            int oq = t & 63;
            float4 s = ((const float4*)&g_part[0][b0 + bl][0])[oq];
#pragma unroll
            for (int sg = 1; sg < NSEG; sg++) {
                float4 v = ((const float4*)&g_part[sg][b0 + bl][0])[oq];
                s.x += v.x; s.y += v.y; s.z += v.z; s.w += v.w;
            }
            float4 bi = ((const float4*)bias)[oq];
            s.x += bi.x; s.y += bi.y; s.z += bi.z; s.w += bi.w;
            ((float4*)&out[(size_t)(b0 + bl) * O_])[oq] = s;
        }
        if (tid == 0) g_cnt[blockIdx.x] = 0;   // re-arm for next replay
    }
}

extern "C" void kernel_launch(void* const* d_in, const int* in_sizes, int n_in,
                              void* d_out, int out_size) {
    const float* x     = (const float*)d_in[0];
    const float* bw    = (const float*)d_in[1];
    const float* coeff = (const float*)d_in[2];
    const float* scale = (const float*)d_in[3];
    const float* bias  = (const float*)d_in[4];
    float* out = (float*)d_out;

    prepack_kernel<<<dim3(I_, KSPLIT), 256>>>(x, coeff, scale, bw);

    dim3 grid(B_ / BTILE, NSEG);   // 32 x 8 = 256 CTAs
    kan_main<<<grid, 512>>>(bias, out);
}

// round 16
// speedup vs baseline: 1.0801x; 1.0801x over previous
#include <cuda_runtime.h>
#include <cuda_fp16.h>
#include <stdint.h>

// Problem constants
#define B_ 1024
#define I_ 256
#define O_ 256
#define K_ 128

#define NSEG 8          // i-segments: grid = 32 b-tiles x 8 = 256 CTAs (0.86 wave at occ 2)
#define ISEG (I_ / NSEG)
#define BTILE 32        // batches per CTA
#define KSPLIT 4        // prepack k-parallelism / prep b-slice

// Per-(b,i) fp32 packed activation [i][b]: (silu, 1-frac, frac, bitcast(l*1024))
__device__ float4 g_pkf[I_ * B_];
// Packed spline pairs [i][k][o] = half2(c[o,i,k]*s, c[o,i,k+1]*s)  (33.5 MB, L2-resident)
__device__ unsigned int g_pre[(size_t)I_ * K_ * O_];
// Transposed base weights [i][o]
__device__ float g_bwT[I_ * O_];
// Exclusive partial sums per i-segment
__device__ float g_part[NSEG][B_][O_];
// Arrival counters per b-tile (reset by the reducing CTA)
__device__ int g_cnt[B_ / BTILE];

__device__ __forceinline__ unsigned int h2bits(__half2 h) {
    return *reinterpret_cast<unsigned int*>(&h);
}
__device__ __forceinline__ float2 bits2f2(unsigned int u) {
    return __half22float2(*reinterpret_cast<__half2*>(&u));
}

// Fused preprocessing: activation prep (one (i,b) per thread) + coefficient prepack
// (one (i, k-chunk, o) per thread) + bw transpose. Grid (I_, KSPLIT) x 256.
__global__ __launch_bounds__(256) void prepack_kernel(
    const float* __restrict__ x,      // [B, I]
    const float* __restrict__ coeff,  // [O, I, K]
    const float* __restrict__ scale,  // [O, I]
    const float* __restrict__ bw)     // [O, I]
{
    const int i = blockIdx.x;
    const int y = blockIdx.y;
    const int o = threadIdx.x;

    // ---- prep slice: b = y*256 + o ----
    {
        const int b = y * 256 + o;
        float xv = __ldg(&x[b * I_ + i]);
        float ax = fabsf(xv);
        float e  = __expf(-2.0f * ax);
        float r  = (1.0f - e) / (1.0f + e);
        float p  = copysignf(r, xv);              // tanh(x) in [-1,1] => clip identity
        float sg = 1.0f / (1.0f + __expf(-p));
        float act = p * sg;                        // silu(p)
        float scaled = fminf(fmaxf((p + 1.0f) * 63.5f, 0.0f), 127.0f);
        int   l    = (int)scaled;
        float frac = scaled - (float)l;
        g_pkf[i * B_ + b] = make_float4(act, 1.0f - frac, frac,
                                        __int_as_float(l * (O_ * 4)));
    }

    // ---- prepack slice: k-chunk [y*32, y*32+32) for output o ----
    const int kb = y * (K_ / KSPLIT);
    const float* src = coeff + ((size_t)o * I_ + i) * (size_t)K_;
    float s = __ldg(&scale[o * I_ + i]);
    unsigned int* dst = g_pre + (size_t)i * (K_ * O_) + (size_t)kb * O_ + o;

    float c[33];
    const float4* s4 = (const float4*)(src + kb);
#pragma unroll
    for (int j = 0; j < 8; j++) {
        float4 v = s4[j];
        c[4 * j] = v.x; c[4 * j + 1] = v.y; c[4 * j + 2] = v.z; c[4 * j + 3] = v.w;
    }
    // Right-tap of the chunk's last k: next element, or wrap (only read at l=127 where frac=0)
    c[32] = (kb + 32 < K_) ? __ldg(src + kb + 32) : __ldg(src);

#pragma unroll
    for (int k = 0; k < 32; k++)
        dst[(size_t)k * O_] = h2bits(__floats2half2_rn(c[k] * s, c[k + 1] * s));

    if (y == 0)
        g_bwT[i * O_ + o] = __ldg(&bw[o * I_ + i]);   // coalesced write
}

// Main: barrier-free hot loop; each lane's LDG.128 gather serves 4 outputs.
// 512 threads = 16 warps: warp = (o-half 0..1, 128 o's) x (b-eighth 0..7, 4 batches).
__global__ __launch_bounds__(512, 2) void kan_main(
    const float* __restrict__ bias, float* __restrict__ out)
{
    __shared__ __align__(16) float4 sPk[ISEG * BTILE];   // 16 KB
    __shared__ int sLast;

    const int tid  = threadIdx.x;
    const int lane = tid & 31;
    const int warp = tid >> 5;
    const int oh   = warp & 1;        // o-half: 128 outputs
    const int be   = warp >> 1;       // b-eighth: 4 batches
    const int ol   = oh * 128 + 4 * lane;   // this lane's 4 outputs (16B aligned)
    const int b0   = blockIdx.x * BTILE;
    const int ibeg = blockIdx.y * ISEG;

    // Stage pk for the whole segment (coalesced LDG.128; only barrier before reduce)
    for (int t = tid; t < ISEG * BTILE; t += 512)
        sPk[t] = g_pkf[(ibeg + (t >> 5)) * B_ + b0 + (t & 31)];
    __syncthreads();

    float acc[4][4];
#pragma unroll
    for (int j = 0; j < 4; j++) {
        acc[j][0] = 0.0f; acc[j][1] = 0.0f; acc[j][2] = 0.0f; acc[j][3] = 0.0f;
    }

    for (int ii = 0; ii < ISEG; ii++) {
        const int i = ibeg + ii;
        const float4 wv = *(const float4*)(g_bwT + i * O_ + ol);   // LDG.128, coalesced
        const char* gbase = (const char*)g_pre + ((size_t)i * (K_ * O_) + ol) * 4u;
        const float4* pkp = sPk + ii * BTILE + be * 4;
#pragma unroll
        for (int bb = 0; bb < 4; bb++) {
            float4 pk = pkp[bb];                                   // LDS.128 broadcast
            uint4 ge = *(const uint4*)(gbase + __float_as_int(pk.w));  // 512B/warp gather
            float2 c0 = bits2f2(ge.x);                             // (c_l*s, c_r*s) per output
            float2 c1 = bits2f2(ge.y);
            float2 c2 = bits2f2(ge.z);
            float2 c3 = bits2f2(ge.w);
            acc[bb][0] = fmaf(pk.y, c0.x, acc[bb][0]);
            acc[bb][0] = fmaf(pk.z, c0.y, acc[bb][0]);
            acc[bb][0] = fmaf(pk.x, wv.x, acc[bb][0]);
            acc[bb][1] = fmaf(pk.y, c1.x, acc[bb][1]);
            acc[bb][1] = fmaf(pk.z, c1.y, acc[bb][1]);
            acc[bb][1] = fmaf(pk.x, wv.y, acc[bb][1]);
            acc[bb][2] = fmaf(pk.y, c2.x, acc[bb][2]);
            acc[bb][2] = fmaf(pk.z, c2.y, acc[bb][2]);
            acc[bb][2] = fmaf(pk.x, wv.z, acc[bb][2]);
            acc[bb][3] = fmaf(pk.y, c3.x, acc[bb][3]);
            acc[bb][3] = fmaf(pk.z, c3.y, acc[bb][3]);
            acc[bb][3] = fmaf(pk.x, wv.w, acc[bb][3]);
        }
    }

    // Exclusive partial slice (contiguous 512B per warp via float4)
#pragma unroll
    for (int bb = 0; bb < 4; bb++)
        *(float4*)(&g_part[blockIdx.y][b0 + be * 4 + bb][ol]) =
            make_float4(acc[bb][0], acc[bb][1], acc[bb][2], acc[bb][3]);

    // Last-arriving CTA of this b-tile reduces the NSEG partials (fixed order, deterministic)
    __threadfence();
    __syncthreads();
    if (tid == 0) {
        int old = atomicAdd(&g_cnt[blockIdx.x], 1);
        sLast = (old == NSEG - 1);
    }
    __syncthreads();
    if (sLast) {
#pragma unroll
        for (int j = 0; j < 4; j++) {
            int t  = tid + 512 * j;          // 2048 float4 = 32 b x 64 f4
            int bl = t >> 6;
            int oq = t & 63;
            float4 s = ((const float4*)&g_part[0][b0 + bl][0])[oq];
#pragma unroll
            for (int sg = 1; sg < NSEG; sg++) {
                float4 v = ((const float4*)&g_part[sg][b0 + bl][0])[oq];
                s.x += v.x; s.y += v.y; s.z += v.z; s.w += v.w;
            }
            float4 bi = ((const float4*)bias)[oq];
            s.x += bi.x; s.y += bi.y; s.z += bi.z; s.w += bi.w;
            ((float4*)&out[(size_t)(b0 + bl) * O_])[oq] = s;
        }
        if (tid == 0) g_cnt[blockIdx.x] = 0;   // re-arm for next replay
    }
}

extern "C" void kernel_launch(void* const* d_in, const int* in_sizes, int n_in,
                              void* d_out, int out_size) {
    const float* x     = (const float*)d_in[0];
    const float* bw    = (const float*)d_in[1];
    const float* coeff = (const float*)d_in[2];
    const float* scale = (const float*)d_in[3];
    const float* bias  = (const float*)d_in[4];
    float* out = (float*)d_out;

    prepack_kernel<<<dim3(I_, KSPLIT), 256>>>(x, coeff, scale, bw);

    dim3 grid(B_ / BTILE, NSEG);   // 32 x 8 = 256 CTAs
    kan_main<<<grid, 512>>>(bias, out);
}